// round 1
// baseline (speedup 1.0000x reference)
#include <cuda_runtime.h>
#include <cuda_bf16.h>

// OctonionFanoCoherence: per batch element b (B = 1M):
//   normalize each of the 7 8-vectors; for each Fano line (i,j,k),
//   err += || oct_mul(x_i, x_j) - x_k ||^2 ; phi = clip(-log(err/7 + 1e-8)*exp(ls), 0, 10)

#define TPB 128          // elements (threads) per block
#define SSTR 57          // smem stride per element (57 mod 32 = 25, coprime -> conflict-free)

__device__ __forceinline__ void qmul(const float* p, const float* q, float* r) {
    r[0] = p[0]*q[0] - p[1]*q[1] - p[2]*q[2] - p[3]*q[3];
    r[1] = p[0]*q[1] + p[1]*q[0] + p[2]*q[3] - p[3]*q[2];
    r[2] = p[0]*q[2] - p[1]*q[3] + p[2]*q[0] + p[3]*q[1];
    r[3] = p[0]*q[3] + p[1]*q[2] - p[2]*q[1] + p[3]*q[0];
}

// Octonion product via Cayley-Dickson (matches reference _oct_structure):
//   z1 = a1*b1 - conj(b2)*a2 ;  z2 = b2*a1 + a2*conj(b1)
__device__ __forceinline__ void omul(const float* x, const float* y, float* z) {
    const float* a1 = x;     const float* a2 = x + 4;
    const float* b1 = y;     const float* b2 = y + 4;
    float t1[4], t2[4];
    qmul(a1, b1, t1);
    float cb2[4] = { b2[0], -b2[1], -b2[2], -b2[3] };
    qmul(cb2, a2, t2);
    z[0] = t1[0] - t2[0]; z[1] = t1[1] - t2[1];
    z[2] = t1[2] - t2[2]; z[3] = t1[3] - t2[3];
    qmul(b2, a1, t1);
    float cb1[4] = { b1[0], -b1[1], -b1[2], -b1[3] };
    qmul(a2, cb1, t2);
    z[4] = t1[0] + t2[0]; z[5] = t1[1] + t2[1];
    z[6] = t1[2] + t2[2]; z[7] = t1[3] + t2[3];
}

__global__ void __launch_bounds__(TPB)
oct_fano_kernel(const float* __restrict__ in,
                const float* __restrict__ log_sens,
                float* __restrict__ out,
                int B)
{
    __shared__ float s[TPB * SSTR];

    const int tid = threadIdx.x;
    const long long blockBase = (long long)blockIdx.x * TPB;
    const int elems = min(TPB, (int)(B - blockBase));     // tail guard (B is divisible, but safe)

    // ---- Stage 1: fully coalesced gmem -> smem ----
    // Each element is 56 floats = 14 float4 (224 B, 16B-aligned since 224 % 16 == 0).
    const float4* in4 = reinterpret_cast<const float4*>(in + blockBase * 56);
    const int n4 = elems * 14;
#pragma unroll
    for (int it = 0; it < 14; ++it) {
        int idx4 = tid + it * TPB;
        if (idx4 < n4) {
            float4 v = in4[idx4];
            int e = idx4 / 14;
            int o = idx4 - e * 14;
            float* dst = &s[e * SSTR + o * 4];
            dst[0] = v.x; dst[1] = v.y; dst[2] = v.z; dst[3] = v.w;
        }
    }
    __syncthreads();

    if (tid >= elems) return;

    // ---- Stage 2: per-thread compute (conflict-free smem reads) ----
    float st[7][8];
    const float* my = &s[tid * SSTR];
#pragma unroll
    for (int l = 0; l < 7; ++l) {
        float acc = 0.f;
#pragma unroll
        for (int c = 0; c < 8; ++c) {
            float v = my[l * 8 + c];
            st[l][c] = v;
            acc = fmaf(v, v, acc);
        }
        // reference: 1 / max(||x||, 1e-12)  ==  rsqrt(max(||x||^2, 1e-24))
        float inv = rsqrtf(fmaxf(acc, 1e-24f));
#pragma unroll
        for (int c = 0; c < 8; ++c) st[l][c] *= inv;
    }

    // Fano lines: (i, j, k)
    const int fi[7] = {0, 1, 2, 3, 4, 5, 6};
    const int fj[7] = {1, 2, 3, 4, 5, 6, 0};
    const int fk[7] = {3, 4, 5, 6, 0, 1, 2};

    float err = 0.f;
#pragma unroll
    for (int l = 0; l < 7; ++l) {
        float p[8];
        omul(st[fi[l]], st[fj[l]], p);
        const float* xk = st[fk[l]];
#pragma unroll
        for (int c = 0; c < 8; ++c) {
            float d = p[c] - xk[c];
            err = fmaf(d, d, err);
        }
    }

    float phi = -logf(err * (1.0f / 7.0f) + 1e-8f) * expf(log_sens[0]);
    phi = fminf(fmaxf(phi, 0.0f), 10.0f);
    out[blockBase + tid] = phi;
}

extern "C" void kernel_launch(void* const* d_in, const int* in_sizes, int n_in,
                              void* d_out, int out_size)
{
    const float* colony   = (const float*)d_in[0];   // [B, 7, 8] fp32
    const float* log_sens = (const float*)d_in[1];   // scalar fp32
    float* out = (float*)d_out;                      // [B] fp32

    int B = in_sizes[0] / 56;
    int blocks = (B + TPB - 1) / TPB;
    oct_fano_kernel<<<blocks, TPB>>>(colony, log_sens, out, B);
}

// round 3
// speedup vs baseline: 1.0078x; 1.0078x over previous
#include <cuda_runtime.h>
#include <cuda_bf16.h>

// OctonionFanoCoherence, reformulated:
//   Octonions form a composition algebra: ||x*y|| = ||x||*||y|| exactly.
//   With x̂ = x/||x||, per Fano line (i,j,k):
//     ||x̂i*x̂j - x̂k||^2 = 2 - 2*dot(x̂i*x̂j, x̂k)
//                       = 2 - 2*dot(omul(xi,xj), xk) * inv_i*inv_j*inv_k
//   avg_error = 2 - (2/7) * sum_l dot_l
//   phi = clip(-log(avg_error + 1e-8) * exp(log_sens), 0, 10)

#define TPB 256

// ---- VERIFIED in round 1 (passed, rel_err 1.6e-6) — do not re-derive ----
__device__ __forceinline__ void qmul(const float* p, const float* q, float* r) {
    r[0] = p[0]*q[0] - p[1]*q[1] - p[2]*q[2] - p[3]*q[3];
    r[1] = p[0]*q[1] + p[1]*q[0] + p[2]*q[3] - p[3]*q[2];
    r[2] = p[0]*q[2] - p[1]*q[3] + p[2]*q[0] + p[3]*q[1];
    r[3] = p[0]*q[3] + p[1]*q[2] - p[2]*q[1] + p[3]*q[0];
}

// Octonion product via Cayley-Dickson (matches reference _oct_structure):
//   z1 = a1*b1 - conj(b2)*a2 ;  z2 = b2*a1 + a2*conj(b1)
__device__ __forceinline__ void omul(const float* x, const float* y, float* z) {
    const float* a1 = x;     const float* a2 = x + 4;
    const float* b1 = y;     const float* b2 = y + 4;
    float t1[4], t2[4];
    qmul(a1, b1, t1);
    float cb2[4] = { b2[0], -b2[1], -b2[2], -b2[3] };
    qmul(cb2, a2, t2);
    z[0] = t1[0] - t2[0]; z[1] = t1[1] - t2[1];
    z[2] = t1[2] - t2[2]; z[3] = t1[3] - t2[3];
    qmul(b2, a1, t1);
    float cb1[4] = { b1[0], -b1[1], -b1[2], -b1[3] };
    qmul(a2, cb1, t2);
    z[4] = t1[0] + t2[0]; z[5] = t1[1] + t2[1];
    z[6] = t1[2] + t2[2]; z[7] = t1[3] + t2[3];
}
// --------------------------------------------------------------------------

__global__ void __launch_bounds__(TPB)
oct_fano_kernel(const float* __restrict__ in,
                const float* __restrict__ log_sens,
                float* __restrict__ out,
                int B)
{
    const int gid = blockIdx.x * TPB + threadIdx.x;
    if (gid >= B) return;

    // ---- Load 56 floats = 14 float4, fully unrolled -> registers, MLP=14 ----
    const float4* p4 = reinterpret_cast<const float4*>(in) + (size_t)gid * 14;
    float x[56];
#pragma unroll
    for (int i = 0; i < 14; ++i) {
        float4 v = __ldg(&p4[i]);
        x[4*i + 0] = v.x; x[4*i + 1] = v.y;
        x[4*i + 2] = v.z; x[4*i + 3] = v.w;
    }

    // ---- Inverse norms of the 7 octonions ----
    float inv[7];
#pragma unroll
    for (int l = 0; l < 7; ++l) {
        float acc = 0.f;
#pragma unroll
        for (int c = 0; c < 8; ++c)
            acc = fmaf(x[l*8 + c], x[l*8 + c], acc);
        // 1/max(||x||,1e-12) == rsqrt(max(||x||^2,1e-24))
        inv[l] = rsqrtf(fmaxf(acc, 1e-24f));
    }

    // ---- Fano lines: (l, l+1 mod 7, l+3 mod 7) ----
    float s = 0.f;
#pragma unroll
    for (int l = 0; l < 7; ++l) {
        const int i = l, j = (l + 1) % 7, k = (l + 3) % 7;
        float p[8];
        omul(&x[i*8], &x[j*8], p);
        const float* xk = &x[k*8];
        float d = 0.f;
#pragma unroll
        for (int c = 0; c < 8; ++c)
            d = fmaf(p[c], xk[c], d);
        s = fmaf(d, inv[i] * inv[j] * inv[k], s);
    }

    // avg_error = (14 - 2*s) / 7 = 2 - (2/7)*s
    float avg = fmaf(s, -2.0f / 7.0f, 2.0f);
    float phi = -logf(avg + 1e-8f) * expf(__ldg(log_sens));
    phi = fminf(fmaxf(phi, 0.0f), 10.0f);
    out[gid] = phi;
}

extern "C" void kernel_launch(void* const* d_in, const int* in_sizes, int n_in,
                              void* d_out, int out_size)
{
    const float* colony   = (const float*)d_in[0];   // [B, 7, 8] fp32
    const float* log_sens = (const float*)d_in[1];   // scalar fp32
    float* out = (float*)d_out;                      // [B] fp32

    int B = in_sizes[0] / 56;
    int blocks = (B + TPB - 1) / TPB;
    oct_fano_kernel<<<blocks, TPB>>>(colony, log_sens, out, B);
}

// round 4
// speedup vs baseline: 1.1223x; 1.1136x over previous
#include <cuda_runtime.h>
#include <cuda_bf16.h>
#include <cstdint>

// OctonionFanoCoherence:
//   Composition algebra: ||x*y|| = ||x||*||y||, so with unit vectors
//   ||x̂i*x̂j - x̂k||^2 = 2 - 2*dot(omul(xi,xj), xk)*inv_i*inv_j*inv_k
//   avg_error = 2 - (2/7)*sum_l dot_l ;  phi = clip(-log(avg+1e-8)*exp(ls), 0, 10)
//
// Memory plan: coalesced cp.async.cg (L1-bypass) fill of smem, 240B-padded
// per-element rows (LDS.128 conflict-free), then per-thread register compute.

#define TPB 128
#define ELEM_F4 14          // 14 float4 = 56 floats of real data
#define ROW_F4  15          // padded to 15 float4 = 240 B (16B-aligned, conflict-free)

// ---- VERIFIED round 1/3 (rel_err ~2e-6) — do not re-derive ----
__device__ __forceinline__ void qmul(const float* p, const float* q, float* r) {
    r[0] = p[0]*q[0] - p[1]*q[1] - p[2]*q[2] - p[3]*q[3];
    r[1] = p[0]*q[1] + p[1]*q[0] + p[2]*q[3] - p[3]*q[2];
    r[2] = p[0]*q[2] - p[1]*q[3] + p[2]*q[0] + p[3]*q[1];
    r[3] = p[0]*q[3] + p[1]*q[2] - p[2]*q[1] + p[3]*q[0];
}
__device__ __forceinline__ void omul(const float* x, const float* y, float* z) {
    const float* a1 = x;     const float* a2 = x + 4;
    const float* b1 = y;     const float* b2 = y + 4;
    float t1[4], t2[4];
    qmul(a1, b1, t1);
    float cb2[4] = { b2[0], -b2[1], -b2[2], -b2[3] };
    qmul(cb2, a2, t2);
    z[0] = t1[0] - t2[0]; z[1] = t1[1] - t2[1];
    z[2] = t1[2] - t2[2]; z[3] = t1[3] - t2[3];
    qmul(b2, a1, t1);
    float cb1[4] = { b1[0], -b1[1], -b1[2], -b1[3] };
    qmul(a2, cb1, t2);
    z[4] = t1[0] + t2[0]; z[5] = t1[1] + t2[1];
    z[6] = t1[2] + t2[2]; z[7] = t1[3] + t2[7-7] + t2[3] - t2[3]; // keep exact: z7 below
}
// NOTE: to avoid any risk of transcription bugs, omul above is replaced by the
// fully verbatim version in omul_v (used by the kernel).
__device__ __forceinline__ void omul_v(const float* x, const float* y, float* z) {
    const float* a1 = x;     const float* a2 = x + 4;
    const float* b1 = y;     const float* b2 = y + 4;
    float t1[4], t2[4];
    qmul(a1, b1, t1);
    float cb2[4] = { b2[0], -b2[1], -b2[2], -b2[3] };
    qmul(cb2, a2, t2);
    z[0] = t1[0] - t2[0]; z[1] = t1[1] - t2[1];
    z[2] = t1[2] - t2[2]; z[3] = t1[3] - t2[3];
    qmul(b2, a1, t1);
    float cb1[4] = { b1[0], -b1[1], -b1[2], -b1[3] };
    qmul(a2, cb1, t2);
    z[4] = t1[0] + t2[0]; z[5] = t1[1] + t2[1];
    z[6] = t1[2] + t2[2]; z[7] = t1[3] + t2[3];
}
// ----------------------------------------------------------------

__global__ void __launch_bounds__(TPB)
oct_fano_kernel(const float* __restrict__ in,
                const float* __restrict__ log_sens,
                float* __restrict__ out,
                int B)
{
    __shared__ float4 s[TPB * ROW_F4];   // 128 * 15 * 16 = 30720 B

    const int tid = threadIdx.x;
    const long long blockBase = (long long)blockIdx.x * TPB;
    const int elems = min(TPB, (int)(B - blockBase));
    const int n4 = elems * ELEM_F4;

    // ---- Stage 1: coalesced cp.async.cg fill (L1 bypass, 16B granules) ----
    const float4* in4 = reinterpret_cast<const float4*>(in) + blockBase * ELEM_F4;
    const uint32_t s_base = (uint32_t)__cvta_generic_to_shared(s);
#pragma unroll
    for (int it = 0; it < ELEM_F4; ++it) {
        int idx4 = tid + it * TPB;               // consecutive lanes -> consecutive gmem
        if (idx4 < n4) {
            int e = idx4 / ELEM_F4;              // mul-shift, cheap
            int o = idx4 - e * ELEM_F4;
            uint32_t dst = s_base + (uint32_t)(e * ROW_F4 + o) * 16u;
            asm volatile("cp.async.cg.shared.global [%0], [%1], 16;\n"
                         :: "r"(dst), "l"(in4 + idx4) : "memory");
        }
    }
    asm volatile("cp.async.commit_group;\n" ::: "memory");
    asm volatile("cp.async.wait_group 0;\n" ::: "memory");
    __syncthreads();

    if (tid >= elems) return;

    // ---- Stage 2: per-thread registers via conflict-free LDS.128 ----
    float x[56];
    const float4* my = &s[tid * ROW_F4];
#pragma unroll
    for (int i = 0; i < ELEM_F4; ++i) {
        float4 v = my[i];
        x[4*i + 0] = v.x; x[4*i + 1] = v.y;
        x[4*i + 2] = v.z; x[4*i + 3] = v.w;
    }

    // ---- Inverse norms of the 7 octonions ----
    float inv[7];
#pragma unroll
    for (int l = 0; l < 7; ++l) {
        float acc = 0.f;
#pragma unroll
        for (int c = 0; c < 8; ++c)
            acc = fmaf(x[l*8 + c], x[l*8 + c], acc);
        inv[l] = rsqrtf(fmaxf(acc, 1e-24f));   // == 1/max(||x||,1e-12)
    }

    // ---- Fano lines (l, l+1 mod 7, l+3 mod 7) ----
    float sacc = 0.f;
#pragma unroll
    for (int l = 0; l < 7; ++l) {
        const int i = l, j = (l + 1) % 7, k = (l + 3) % 7;
        float p[8];
        omul_v(&x[i*8], &x[j*8], p);
        const float* xk = &x[k*8];
        float d = 0.f;
#pragma unroll
        for (int c = 0; c < 8; ++c)
            d = fmaf(p[c], xk[c], d);
        sacc = fmaf(d, inv[i] * inv[j] * inv[k], sacc);
    }

    // avg_error = 2 - (2/7)*sacc
    float avg = fmaf(sacc, -2.0f / 7.0f, 2.0f);
    float phi = -logf(avg + 1e-8f) * expf(__ldg(log_sens));
    phi = fminf(fmaxf(phi, 0.0f), 10.0f);
    out[blockBase + tid] = phi;
}

extern "C" void kernel_launch(void* const* d_in, const int* in_sizes, int n_in,
                              void* d_out, int out_size)
{
    const float* colony   = (const float*)d_in[0];   // [B, 7, 8] fp32
    const float* log_sens = (const float*)d_in[1];   // scalar fp32
    float* out = (float*)d_out;                      // [B] fp32

    int B = in_sizes[0] / 56;
    int blocks = (B + TPB - 1) / TPB;
    oct_fano_kernel<<<blocks, TPB>>>(colony, log_sens, out, B);
}